// round 7
// baseline (speedup 1.0000x reference)
#include <cuda_runtime.h>
#include <cuda_fp16.h>
#include <cstdint>

// out[b,n,f] = sum_m A[b,n,m] * X[b,m,f] + bias[f]
// A: [8,4096,4096] fp32, X: [8,4096,64] fp32, bias [64].
//
// Single fused kernel (no prep pass): R5 structure (fp16 mma.sync, register-
// staged double buffer, KC=64, exact-fit 296-CTA grid = 2/SM) with B built
// in-kernel each chunk: LDG X fp32 [k][f] -> cvt fp16 -> STS natural [k][f]
// rows; B fragments loaded via ldmatrix.x4.TRANS (transpose on load).

#define NBATCH  8
#define NN      4096
#define FF      64
#define KC      64
#define NCH     (NN / KC)       // 64
#define CTAS_B  37              // grid = 296 = 2*148
#define MAXG    7

#define AST     (MAXG * 16 * 128)   // 14336 B: 112 m-rows x 64 k fp16
#define BST     (KC * 128)          // 8192 B:  64 k-rows x 64 f fp16
#define STB     (AST + BST)         // 22528
#define SMEM_DYN (2 * STB)          // 45056

__device__ __forceinline__ uint32_t smem_u32(const void* p) {
    uint32_t a;
    asm("{ .reg .u64 t; cvta.to.shared.u64 t, %1; cvt.u32.u64 %0, t; }"
        : "=r"(a) : "l"(p));
    return a;
}
#define SW(o) ((o) ^ (((o) >> 3) & 0x70))

__global__ __launch_bounds__(256, 2) void gemm_f16_fused(
    const float* __restrict__ A,
    const float* __restrict__ X,
    const float* __restrict__ bias,
    float* __restrict__ out)
{
    extern __shared__ char ds[];
    const uint32_t sb = smem_u32(ds);

    const int tid  = threadIdx.x;
    const int wid  = tid >> 5;
    const int lane = tid & 31;

    const int b  = blockIdx.x / CTAS_B;
    const int ct = blockIdx.x % CTAS_B;
    const int g0 = (ct * 256) / CTAS_B;
    const int g1 = ((ct + 1) * 256) / CTAS_B;
    const int NG = g1 - g0;             // 6 or 7
    const int nrows = NG * 16;

    const float* Ab = A + ((size_t)b * NN + (size_t)g0 * 16) * NN;
    const float* Xb = X + (size_t)b * NN * FF;

    // A producer addressing (constant per thread)
    const int arow = tid >> 4;    // A: row base 0..15 (+16*i), 16 float4/row
    const int ac4  = tid & 15;    //    float4 index within row
    // B producer addressing: 64 k-rows x 4 threads/row, 16 f each
    const int bkr = tid >> 2;           // k-row 0..63
    const int bf  = (tid & 3) * 16;     // f start: 0,16,32,48
    const float* b_src = Xb + (size_t)bkr * FF + bf;

    // ldmatrix lane decomposition
    const int li = lane >> 3;     // matrix id 0..3
    const int lr = lane & 7;      // row within matrix
    // A (non-trans, [m][k] rows of 128B):
    const uint32_t a_off =
        (uint32_t)((wid * 16 + (li & 1) * 8 + lr) * 128 + (li >> 1) * 16);
    // B (trans, [k][f] rows of 128B): m0=(k0-7,f0-7) m1=(k8-15,f0-7)
    //                                 m2=(k0-7,f8-15) m3=(k8-15,f8-15)
    const uint32_t b_off =
        (uint32_t)(((li & 1) * 8 + lr) * 128 + (li >> 1) * 16);

    float acc[8][4];
#pragma unroll
    for (int n = 0; n < 8; ++n)
#pragma unroll
        for (int j = 0; j < 4; ++j) acc[n][j] = 0.0f;

    float4 pa[MAXG];
    float4 pb[4];

    // ---- prologue: load + stage chunk 0 ----
#pragma unroll
    for (int i = 0; i < MAXG; ++i)
        if (16 * i < nrows)
            pa[i] = *reinterpret_cast<const float4*>(
                Ab + (size_t)(arow + 16 * i) * NN + ac4 * 4);
#pragma unroll
    for (int i = 0; i < 4; ++i)
        pb[i] = *reinterpret_cast<const float4*>(b_src + 4 * i);
    {
        const uint32_t as = sb, bs = sb + AST;
#pragma unroll
        for (int i = 0; i < MAXG; ++i)
            if (16 * i < nrows) {
                __half2 h0 = __floats2half2_rn(pa[i].x, pa[i].y);
                __half2 h1 = __floats2half2_rn(pa[i].z, pa[i].w);
                const uint32_t off =
                    as + SW((uint32_t)((arow + 16 * i) * 128 + ac4 * 8));
                asm volatile("st.shared.v2.b32 [%0], {%1, %2};" :: "r"(off),
                             "r"(*(uint32_t*)&h0), "r"(*(uint32_t*)&h1) : "memory");
            }
        {
            __half2 q0 = __floats2half2_rn(pb[0].x, pb[0].y);
            __half2 q1 = __floats2half2_rn(pb[0].z, pb[0].w);
            __half2 q2 = __floats2half2_rn(pb[1].x, pb[1].y);
            __half2 q3 = __floats2half2_rn(pb[1].z, pb[1].w);
            __half2 q4 = __floats2half2_rn(pb[2].x, pb[2].y);
            __half2 q5 = __floats2half2_rn(pb[2].z, pb[2].w);
            __half2 q6 = __floats2half2_rn(pb[3].x, pb[3].y);
            __half2 q7 = __floats2half2_rn(pb[3].z, pb[3].w);
            const uint32_t o0 = bs + SW((uint32_t)(bkr * 128 + bf * 2));
            const uint32_t o1 = bs + SW((uint32_t)(bkr * 128 + bf * 2 + 16));
            asm volatile("st.shared.v4.b32 [%0], {%1,%2,%3,%4};" :: "r"(o0),
                         "r"(*(uint32_t*)&q0), "r"(*(uint32_t*)&q1),
                         "r"(*(uint32_t*)&q2), "r"(*(uint32_t*)&q3) : "memory");
            asm volatile("st.shared.v4.b32 [%0], {%1,%2,%3,%4};" :: "r"(o1),
                         "r"(*(uint32_t*)&q4), "r"(*(uint32_t*)&q5),
                         "r"(*(uint32_t*)&q6), "r"(*(uint32_t*)&q7) : "memory");
        }
    }
    __syncthreads();

    for (int c = 0; c < NCH; ++c) {
        // prefetch next chunk into registers
        if (c + 1 < NCH) {
            const int kn = (c + 1) * KC;
#pragma unroll
            for (int i = 0; i < MAXG; ++i)
                if (16 * i < nrows)
                    pa[i] = *reinterpret_cast<const float4*>(
                        Ab + (size_t)(arow + 16 * i) * NN + kn + ac4 * 4);
#pragma unroll
            for (int i = 0; i < 4; ++i)
                pb[i] = *reinterpret_cast<const float4*>(
                    b_src + (size_t)kn * FF + 4 * i);
        }

        // compute chunk c from stage (c&1)
        if (wid < NG) {
            const uint32_t as = sb + (uint32_t)(c & 1) * STB;
            const uint32_t bs = as + AST;
#pragma unroll
            for (int ks = 0; ks < 4; ++ks) {
                uint32_t a0, a1, a2, a3;
                asm volatile(
                    "ldmatrix.sync.aligned.m8n8.x4.shared.b16 {%0,%1,%2,%3}, [%4];"
                    : "=r"(a0), "=r"(a1), "=r"(a2), "=r"(a3)
                    : "r"(as + SW(a_off + (uint32_t)ks * 32)));
#pragma unroll
                for (int p = 0; p < 4; ++p) {
                    uint32_t b0, b1, b2, b3;
                    asm volatile(
                        "ldmatrix.sync.aligned.m8n8.x4.trans.shared.b16 "
                        "{%0,%1,%2,%3}, [%4];"
                        : "=r"(b0), "=r"(b1), "=r"(b2), "=r"(b3)
                        : "r"(bs + SW(b_off + (uint32_t)ks * 2048 + (uint32_t)p * 32)));
                    asm volatile(
                        "mma.sync.aligned.m16n8k16.row.col.f32.f16.f16.f32 "
                        "{%0,%1,%2,%3}, {%4,%5,%6,%7}, {%8,%9}, {%0,%1,%2,%3};"
                        : "+f"(acc[2*p][0]), "+f"(acc[2*p][1]),
                          "+f"(acc[2*p][2]), "+f"(acc[2*p][3])
                        : "r"(a0), "r"(a1), "r"(a2), "r"(a3), "r"(b0), "r"(b1));
                    asm volatile(
                        "mma.sync.aligned.m16n8k16.row.col.f32.f16.f16.f32 "
                        "{%0,%1,%2,%3}, {%4,%5,%6,%7}, {%8,%9}, {%0,%1,%2,%3};"
                        : "+f"(acc[2*p+1][0]), "+f"(acc[2*p+1][1]),
                          "+f"(acc[2*p+1][2]), "+f"(acc[2*p+1][3])
                        : "r"(a0), "r"(a1), "r"(a2), "r"(a3), "r"(b2), "r"(b3));
                }
            }
        }

        // stage chunk c+1 into the other buffer
        if (c + 1 < NCH) {
            const uint32_t as2 = sb + (uint32_t)((c + 1) & 1) * STB;
            const uint32_t bs2 = as2 + AST;
#pragma unroll
            for (int i = 0; i < MAXG; ++i)
                if (16 * i < nrows) {
                    __half2 h0 = __floats2half2_rn(pa[i].x, pa[i].y);
                    __half2 h1 = __floats2half2_rn(pa[i].z, pa[i].w);
                    const uint32_t off =
                        as2 + SW((uint32_t)((arow + 16 * i) * 128 + ac4 * 8));
                    asm volatile("st.shared.v2.b32 [%0], {%1, %2};" :: "r"(off),
                                 "r"(*(uint32_t*)&h0), "r"(*(uint32_t*)&h1)
                                 : "memory");
                }
            {
                __half2 q0 = __floats2half2_rn(pb[0].x, pb[0].y);
                __half2 q1 = __floats2half2_rn(pb[0].z, pb[0].w);
                __half2 q2 = __floats2half2_rn(pb[1].x, pb[1].y);
                __half2 q3 = __floats2half2_rn(pb[1].z, pb[1].w);
                __half2 q4 = __floats2half2_rn(pb[2].x, pb[2].y);
                __half2 q5 = __floats2half2_rn(pb[2].z, pb[2].w);
                __half2 q6 = __floats2half2_rn(pb[3].x, pb[3].y);
                __half2 q7 = __floats2half2_rn(pb[3].z, pb[3].w);
                const uint32_t o0 = bs2 + SW((uint32_t)(bkr * 128 + bf * 2));
                const uint32_t o1 = bs2 + SW((uint32_t)(bkr * 128 + bf * 2 + 16));
                asm volatile("st.shared.v4.b32 [%0], {%1,%2,%3,%4};" :: "r"(o0),
                             "r"(*(uint32_t*)&q0), "r"(*(uint32_t*)&q1),
                             "r"(*(uint32_t*)&q2), "r"(*(uint32_t*)&q3) : "memory");
                asm volatile("st.shared.v4.b32 [%0], {%1,%2,%3,%4};" :: "r"(o1),
                             "r"(*(uint32_t*)&q4), "r"(*(uint32_t*)&q5),
                             "r"(*(uint32_t*)&q6), "r"(*(uint32_t*)&q7) : "memory");
            }
        }
        __syncthreads();
    }

    // ---- epilogue: add bias, store ----
    if (wid < NG) {
        const int g = lane >> 2, q = lane & 3;
        const int mlo = (g0 + wid) * 16 + g;
        float* o0 = out + ((size_t)b * NN + mlo) * FF;
        float* o1 = o0 + (size_t)8 * FF;
#pragma unroll
        for (int nt = 0; nt < 8; ++nt) {
            const int col = nt * 8 + q * 2;
            const float2 bv = *reinterpret_cast<const float2*>(bias + col);
            float2 v0 = make_float2(acc[nt][0] + bv.x, acc[nt][1] + bv.y);
            float2 v1 = make_float2(acc[nt][2] + bv.x, acc[nt][3] + bv.y);
            *reinterpret_cast<float2*>(o0 + col) = v0;
            *reinterpret_cast<float2*>(o1 + col) = v1;
        }
    }
}

extern "C" void kernel_launch(void* const* d_in, const int* in_sizes, int n_in,
                              void* d_out, int out_size)
{
    const float* A    = (const float*)d_in[0]; // adjacent [8,4096,4096]
    const float* X    = (const float*)d_in[1]; // annotations [8,4096,64]
    const float* bias = (const float*)d_in[2]; // bias [1,1,64]
    float* out = (float*)d_out;

    cudaFuncSetAttribute(gemm_f16_fused,
                         cudaFuncAttributeMaxDynamicSharedMemorySize, SMEM_DYN);

    gemm_f16_fused<<<NBATCH * CTAS_B, 256, SMEM_DYN>>>(A, X, bias, out);
}

// round 8
// speedup vs baseline: 1.0048x; 1.0048x over previous
#include <cuda_runtime.h>
#include <cuda_fp16.h>
#include <cstdint>

// out[b,n,f] = sum_m A[b,n,m] * X[b,m,f] + bias[f]
// A: [8,4096,4096] fp32, X: [8,4096,64] fp32, bias [64].
//
// fp16 mma.sync GEMM. Key change vs R5: each compute warp owns 32 M-rows
// (64 acc regs) so the B tile ldmatrix traffic (8KB/chunk/warp) is amortized
// over 2x rows -> ~22% less L1 traffic per DRAM byte (L1 was co-saturating
// with DRAM). B arrives via cp.async from fp16 g_Xt (no regs, no STS);
// A keeps the proven register-staged LDG->cvt->STS path, split in two pa[4]
// waves to fit the 128-reg occ-2 budget. Grid 296 = 2/SM exact fit.

#define NBATCH  8
#define NN      4096
#define FF      64
#define KC      64
#define NCH     (NN / KC)      // 64
#define CTAS_B  37             // grid = 296 = 2*148
#define GPB     128            // 32-row groups per batch

#define A16_ST  16384          // 128 rows x 128B fp16
#define B16_ST  8192           // 64 f-rows x 128B fp16
#define STB     (A16_ST + B16_ST)
#define SMEM_DYN (2 * STB)     // 49152

__device__ __half g_Xt[NBATCH * FF * NN];   // [b][f][k] fp16

__device__ __forceinline__ uint32_t smem_u32(const void* p) {
    uint32_t a;
    asm("{ .reg .u64 t; cvta.to.shared.u64 t, %1; cvt.u32.u64 %0, t; }"
        : "=r"(a) : "l"(p));
    return a;
}
#define SW(o) ((o) ^ (((o) >> 3) & 0x70))

#define CPB16(dst, src) \
    asm volatile("cp.async.cg.shared.global [%0], [%1], 16;" \
                 :: "r"(dst), "l"(src) : "memory")
#define CP_COMMIT() asm volatile("cp.async.commit_group;" ::: "memory")
#define CP_WAIT0()  asm volatile("cp.async.wait_group 0;" ::: "memory")

// ---------- prep: Xt[b][f][k] = fp16(X[b][k][f]) ----------
__global__ __launch_bounds__(256) void prep_xt_kernel(const float* __restrict__ X) {
    __shared__ float t[32][FF + 1];
    const int b  = blockIdx.y;
    const int k0 = blockIdx.x * 32;
    const int tx = threadIdx.x;
    const int ty = threadIdx.y;
#pragma unroll
    for (int i = 0; i < 4; ++i) {
        const int r = ty + 8 * i;
        const float* src = X + ((size_t)b * NN + k0 + r) * FF;
        t[r][tx]      = src[tx];
        t[r][tx + 32] = src[tx + 32];
    }
    __syncthreads();
#pragma unroll
    for (int j = 0; j < 8; ++j) {
        const int f = ty + 8 * j;
        g_Xt[((size_t)b * FF + f) * NN + k0 + tx] = __float2half_rn(t[tx][f]);
    }
}

// ---------- main GEMM ----------
__global__ __launch_bounds__(256, 2) void gemm_f16_m32(
    const float* __restrict__ A,
    const float* __restrict__ bias,
    float* __restrict__ out)
{
    extern __shared__ char ds[];
    const uint32_t sb = smem_u32(ds);

    const int tid  = threadIdx.x;
    const int wid  = tid >> 5;
    const int lane = tid & 31;

    const int b  = blockIdx.x / CTAS_B;
    const int ct = blockIdx.x % CTAS_B;
    const int g0 = (ct * GPB) / CTAS_B;
    const int g1 = ((ct + 1) * GPB) / CTAS_B;
    const int NG = g1 - g0;                 // 3 or 4 (32-row groups)
    const int nrows = NG * 32;

    const float*  Ab  = A + ((size_t)b * NN + (size_t)g0 * 32) * NN;
    const __half* XtB = g_Xt + (size_t)b * FF * NN;

    // A producer: pass i covers rows 16i..16i+15 (i=0..7); thread owns
    // (row arow+16i, float4 slot ac4). Waves: paA = passes 0-3, paB = 4-7.
    const int arow = tid >> 4;
    const int ac4  = tid & 15;
    const uint32_t a_sts = SW((uint32_t)(arow * 128 + ac4 * 8));  // + i*2048
    const float* a_ld = Ab + (size_t)arow * NN + ac4 * 4;          // + i*16*NN

    // B cp.async: 2 x 16B segs per thread per chunk
    const int bn0 = tid >> 3,        bs0 = tid & 7;
    const int bn1 = (tid + 256) >> 3, bs1 = (tid + 256) & 7;
    const uint32_t b_dst0 = SW((uint32_t)(bn0 * 128 + bs0 * 16));
    const uint32_t b_dst1 = SW((uint32_t)(bn1 * 128 + bs1 * 16));
    const __half* b_src0 = XtB + (size_t)bn0 * NN + bs0 * 8;
    const __half* b_src1 = XtB + (size_t)bn1 * NN + bs1 * 8;

    // ldmatrix lane decomposition
    const int li = lane >> 3;
    const int lr = lane & 7;
    const uint32_t a_off0 =
        (uint32_t)((wid * 32 + (li & 1) * 8 + lr) * 128 + (li >> 1) * 16);
    const uint32_t a_off1 = a_off0 + 16 * 128;
    const uint32_t b_off =
        (uint32_t)(((li >> 1) * 8 + lr) * 128 + (li & 1) * 16);

    float acc[2][8][4];
#pragma unroll
    for (int t = 0; t < 2; ++t)
#pragma unroll
        for (int n = 0; n < 8; ++n)
#pragma unroll
            for (int j = 0; j < 4; ++j) acc[t][n][j] = 0.0f;

    float4 pa[4];

    // ---- prologue ----
    // B(0) -> stage0
    CPB16(sb + A16_ST + b_dst0, b_src0);
    CPB16(sb + A16_ST + b_dst1, b_src1);
    CP_COMMIT();
    // A(0) both halves (one-time stalls OK)
#pragma unroll
    for (int i = 0; i < 4; ++i)
        pa[i] = *reinterpret_cast<const float4*>(a_ld + (size_t)(16 * i) * NN);
#pragma unroll
    for (int i = 0; i < 4; ++i) {
        __half2 h0 = __floats2half2_rn(pa[i].x, pa[i].y);
        __half2 h1 = __floats2half2_rn(pa[i].z, pa[i].w);
        asm volatile("st.shared.v2.b32 [%0], {%1, %2};"
                     :: "r"(sb + a_sts + (uint32_t)i * 2048),
                        "r"(*(uint32_t*)&h0), "r"(*(uint32_t*)&h1) : "memory");
    }
#pragma unroll
    for (int i = 4; i < 8; ++i)
        if (16 * i < nrows) {
            float4 v = *reinterpret_cast<const float4*>(a_ld + (size_t)(16 * i) * NN);
            __half2 h0 = __floats2half2_rn(v.x, v.y);
            __half2 h1 = __floats2half2_rn(v.z, v.w);
            asm volatile("st.shared.v2.b32 [%0], {%1, %2};"
                         :: "r"(sb + a_sts + (uint32_t)i * 2048),
                            "r"(*(uint32_t*)&h0), "r"(*(uint32_t*)&h1) : "memory");
        }
    // preload A(1) first half
#pragma unroll
    for (int i = 0; i < 4; ++i)
        pa[i] = *reinterpret_cast<const float4*>(a_ld + (size_t)(16 * i) * NN + KC);
    CP_WAIT0();
    __syncthreads();

    for (int c = 0; c < NCH; ++c) {
        const uint32_t cur = sb + (uint32_t)(c & 1) * STB;
        const uint32_t nxt = sb + (uint32_t)((c + 1) & 1) * STB;

        // issue B(c+1) into nxt (compute c-1 on nxt's buffer finished at barrier)
        if (c + 1 < NCH) {
            const __half* bs_ = b_src0 + (size_t)(c + 1) * KC;
            const __half* bs2 = b_src1 + (size_t)(c + 1) * KC;
            CPB16(nxt + A16_ST + b_dst0, bs_);
            CPB16(nxt + A16_ST + b_dst1, bs2);
        }
        CP_COMMIT();

        // ---- compute ks 0,1 ----
        if (wid < NG) {
#pragma unroll
            for (int ks = 0; ks < 2; ++ks) {
                uint32_t a0, a1, a2, a3, c0, c1, c2, c3;
                asm volatile(
                    "ldmatrix.sync.aligned.m8n8.x4.shared.b16 {%0,%1,%2,%3}, [%4];"
                    : "=r"(a0), "=r"(a1), "=r"(a2), "=r"(a3)
                    : "r"(cur + SW(a_off0 + (uint32_t)ks * 32)));
                asm volatile(
                    "ldmatrix.sync.aligned.m8n8.x4.shared.b16 {%0,%1,%2,%3}, [%4];"
                    : "=r"(c0), "=r"(c1), "=r"(c2), "=r"(c3)
                    : "r"(cur + SW(a_off1 + (uint32_t)ks * 32)));
#pragma unroll
                for (int p = 0; p < 4; ++p) {
                    uint32_t b0, b1, b2, b3;
                    asm volatile(
                        "ldmatrix.sync.aligned.m8n8.x4.shared.b16 {%0,%1,%2,%3}, [%4];"
                        : "=r"(b0), "=r"(b1), "=r"(b2), "=r"(b3)
                        : "r"(cur + A16_ST +
                              SW(b_off + (uint32_t)p * 2048 + (uint32_t)ks * 32)));
                    asm volatile(
                        "mma.sync.aligned.m16n8k16.row.col.f32.f16.f16.f32 "
                        "{%0,%1,%2,%3}, {%4,%5,%6,%7}, {%8,%9}, {%0,%1,%2,%3};"
                        : "+f"(acc[0][2*p][0]), "+f"(acc[0][2*p][1]),
                          "+f"(acc[0][2*p][2]), "+f"(acc[0][2*p][3])
                        : "r"(a0), "r"(a1), "r"(a2), "r"(a3), "r"(b0), "r"(b1));
                    asm volatile(
                        "mma.sync.aligned.m16n8k16.row.col.f32.f16.f16.f32 "
                        "{%0,%1,%2,%3}, {%4,%5,%6,%7}, {%8,%9}, {%0,%1,%2,%3};"
                        : "+f"(acc[0][2*p+1][0]), "+f"(acc[0][2*p+1][1]),
                          "+f"(acc[0][2*p+1][2]), "+f"(acc[0][2*p+1][3])
                        : "r"(a0), "r"(a1), "r"(a2), "r"(a3), "r"(b2), "r"(b3));
                    asm volatile(
                        "mma.sync.aligned.m16n8k16.row.col.f32.f16.f16.f32 "
                        "{%0,%1,%2,%3}, {%4,%5,%6,%7}, {%8,%9}, {%0,%1,%2,%3};"
                        : "+f"(acc[1][2*p][0]), "+f"(acc[1][2*p][1]),
                          "+f"(acc[1][2*p][2]), "+f"(acc[1][2*p][3])
                        : "r"(c0), "r"(c1), "r"(c2), "r"(c3), "r"(b0), "r"(b1));
                    asm volatile(
                        "mma.sync.aligned.m16n8k16.row.col.f32.f16.f16.f32 "
                        "{%0,%1,%2,%3}, {%4,%5,%6,%7}, {%8,%9}, {%0,%1,%2,%3};"
                        : "+f"(acc[1][2*p+1][0]), "+f"(acc[1][2*p+1][1]),
                          "+f"(acc[1][2*p+1][2]), "+f"(acc[1][2*p+1][3])
                        : "r"(c0), "r"(c1), "r"(c2), "r"(c3), "r"(b2), "r"(b3));
                }
            }
        }

        // stage A(c+1) first half (preloaded in pa); load second half
        if (c + 1 < NCH) {
#pragma unroll
            for (int i = 0; i < 4; ++i) {
                __half2 h0 = __floats2half2_rn(pa[i].x, pa[i].y);
                __half2 h1 = __floats2half2_rn(pa[i].z, pa[i].w);
                asm volatile("st.shared.v2.b32 [%0], {%1, %2};"
                             :: "r"(nxt + a_sts + (uint32_t)i * 2048),
                                "r"(*(uint32_t*)&h0), "r"(*(uint32_t*)&h1)
                             : "memory");
            }
#pragma unroll
            for (int i = 0; i < 4; ++i)
                if (16 * (i + 4) < nrows)
                    pa[i] = *reinterpret_cast<const float4*>(
                        a_ld + (size_t)(16 * (i + 4)) * NN + (size_t)(c + 1) * KC);
        }

        // ---- compute ks 2,3 ----
        if (wid < NG) {
#pragma unroll
            for (int ks = 2; ks < 4; ++ks) {
                uint32_t a0, a1, a2, a3, c0, c1, c2, c3;
                asm volatile(
                    "ldmatrix.sync.aligned.m8n8.x4.shared.b16 {%0,%1,%2,%3}, [%4];"
                    : "=r"(a0), "=r"(a1), "=r"(a2), "=r"(a3)
                    : "r"(cur + SW(a_off0 + (uint32_t)ks * 32)));
                asm volatile(
                    "ldmatrix.sync.aligned.m8n8.x4.shared.b16 {%0,%1,%2,%3}, [%4];"
                    : "=r"(c0), "=r"(c1), "=r"(c2), "=r"(c3)
                    : "r"(cur + SW(a_off1 + (uint32_t)ks * 32)));
#pragma unroll
                for (int p = 0; p < 4; ++p) {
                    uint32_t b0, b1, b2, b3;
                    asm volatile(
                        "ldmatrix.sync.aligned.m8n8.x4.shared.b16 {%0,%1,%2,%3}, [%4];"
                        : "=r"(b0), "=r"(b1), "=r"(b2), "=r"(b3)
                        : "r"(cur + A16_ST +
                              SW(b_off + (uint32_t)p * 2048 + (uint32_t)ks * 32)));
                    asm volatile(
                        "mma.sync.aligned.m16n8k16.row.col.f32.f16.f16.f32 "
                        "{%0,%1,%2,%3}, {%4,%5,%6,%7}, {%8,%9}, {%0,%1,%2,%3};"
                        : "+f"(acc[0][2*p][0]), "+f"(acc[0][2*p][1]),
                          "+f"(acc[0][2*p][2]), "+f"(acc[0][2*p][3])
                        : "r"(a0), "r"(a1), "r"(a2), "r"(a3), "r"(b0), "r"(b1));
                    asm volatile(
                        "mma.sync.aligned.m16n8k16.row.col.f32.f16.f16.f32 "
                        "{%0,%1,%2,%3}, {%4,%5,%6,%7}, {%8,%9}, {%0,%1,%2,%3};"
                        : "+f"(acc[0][2*p+1][0]), "+f"(acc[0][2*p+1][1]),
                          "+f"(acc[0][2*p+1][2]), "+f"(acc[0][2*p+1][3])
                        : "r"(a0), "r"(a1), "r"(a2), "r"(a3), "r"(b2), "r"(b3));
                    asm volatile(
                        "mma.sync.aligned.m16n8k16.row.col.f32.f16.f16.f32 "
                        "{%0,%1,%2,%3}, {%4,%5,%6,%7}, {%8,%9}, {%0,%1,%2,%3};"
                        : "+f"(acc[1][2*p][0]), "+f"(acc[1][2*p][1]),
                          "+f"(acc[1][2*p][2]), "+f"(acc[1][2*p][3])
                        : "r"(c0), "r"(c1), "r"(c2), "r"(c3), "r"(b0), "r"(b1));
                    asm volatile(
                        "mma.sync.aligned.m16n8k16.row.col.f32.f16.f16.f32 "
                        "{%0,%1,%2,%3}, {%4,%5,%6,%7}, {%8,%9}, {%0,%1,%2,%3};"
                        : "+f"(acc[1][2*p+1][0]), "+f"(acc[1][2*p+1][1]),
                          "+f"(acc[1][2*p+1][2]), "+f"(acc[1][2*p+1][3])
                        : "r"(c0), "r"(c1), "r"(c2), "r"(c3), "r"(b2), "r"(b3));
                }
            }
        }

        CP_WAIT0();   // B(c+1) landed

        // stage A(c+1) second half; preload A(c+2) first half
        if (c + 1 < NCH) {
#pragma unroll
            for (int i = 0; i < 4; ++i)
                if (16 * (i + 4) < nrows) {
                    __half2 h0 = __floats2half2_rn(pa[i].x, pa[i].y);
                    __half2 h1 = __floats2half2_rn(pa[i].z, pa[i].w);
                    asm volatile("st.shared.v2.b32 [%0], {%1, %2};"
                                 :: "r"(nxt + a_sts + (uint32_t)(i + 4) * 2048),
                                    "r"(*(uint32_t*)&h0), "r"(*(uint32_t*)&h1)
                                 : "memory");
                }
            if (c + 2 < NCH) {
#pragma unroll
                for (int i = 0; i < 4; ++i)
                    pa[i] = *reinterpret_cast<const float4*>(
                        a_ld + (size_t)(16 * i) * NN + (size_t)(c + 2) * KC);
            }
        }
        __syncthreads();
    }

    // ---- epilogue: add bias, store ----
    if (wid < NG) {
        const int g = lane >> 2, q = lane & 3;
#pragma unroll
        for (int t = 0; t < 2; ++t) {
            const int mlo = (g0 + wid) * 32 + 16 * t + g;
            float* o0 = out + ((size_t)b * NN + mlo) * FF;
            float* o1 = o0 + (size_t)8 * FF;
#pragma unroll
            for (int nt = 0; nt < 8; ++nt) {
                const int col = nt * 8 + q * 2;
                const float2 bv = *reinterpret_cast<const float2*>(bias + col);
                float2 v0 = make_float2(acc[t][nt][0] + bv.x, acc[t][nt][1] + bv.y);
                float2 v1 = make_float2(acc[t][nt][2] + bv.x, acc[t][nt][3] + bv.y);
                *reinterpret_cast<float2*>(o0 + col) = v0;
                *reinterpret_cast<float2*>(o1 + col) = v1;
            }
        }
    }
}

extern "C" void kernel_launch(void* const* d_in, const int* in_sizes, int n_in,
                              void* d_out, int out_size)
{
    const float* A    = (const float*)d_in[0]; // adjacent [8,4096,4096]
    const float* X    = (const float*)d_in[1]; // annotations [8,4096,64]
    const float* bias = (const float*)d_in[2]; // bias [1,1,64]
    float* out = (float*)d_out;

    cudaFuncSetAttribute(gemm_f16_m32,
                         cudaFuncAttributeMaxDynamicSharedMemorySize, SMEM_DYN);

    dim3 pg(NN / 32, NBATCH);
    dim3 pbk(32, 8);
    prep_xt_kernel<<<pg, pbk>>>(X);

    gemm_f16_m32<<<NBATCH * CTAS_B, 256, SMEM_DYN>>>(A, bias, out);
}

// round 9
// speedup vs baseline: 1.0986x; 1.0934x over previous
#include <cuda_runtime.h>
#include <cuda_fp16.h>
#include <cstdint>

// out[b,n,f] = sum_m A[b,n,m] * X[b,m,f] + bias[f]
// A: [8,4096,4096] fp32, X: [8,4096,64] fp32, bias [64].
//
// R5 core (fp16 mma.sync, register-staged, exact-fit 296-CTA grid, 16-row
// balanced split) with TWO KC=64 sub-chunks per pipeline iteration: one
// __syncthreads per 128 k (32 barriers instead of 64). Each stage buffer =
// two verbatim R5 sub-tiles; register staging (pa[7]+pb[2]) cycles twice per
// iteration, preserving R5's LDG->STS latency window exactly.

#define NBATCH  8
#define NN      4096
#define FF      64
#define CTAS_B  37              // grid = 296 = 2*148
#define MAXG    7
#define NSUB    64              // KC=64 sub-chunks
#define NIT     32              // 2 sub-chunks per iteration

#define SUB_A   14336           // 112 rows x 128B fp16
#define SUB_B   8192            // 64 f-rows x 128B fp16
#define STB2    (2 * (SUB_A + SUB_B))   // 45056 per stage
#define OFF_B   (2 * SUB_A)             // 28672 within stage
#define SMEM_DYN (2 * STB2)             // 90112

__device__ __half g_Xt[NBATCH * FF * NN];   // [b][f][k] fp16

__device__ __forceinline__ uint32_t smem_u32(const void* p) {
    uint32_t a;
    asm("{ .reg .u64 t; cvta.to.shared.u64 t, %1; cvt.u32.u64 %0, t; }"
        : "=r"(a) : "l"(p));
    return a;
}
#define SW(o) ((o) ^ (((o) >> 3) & 0x70))

// ---------- prep: Xt[b][f][k] = fp16(X[b][k][f]) ----------
__global__ __launch_bounds__(256) void prep_xt_kernel(const float* __restrict__ X) {
    __shared__ float t[32][FF + 1];
    const int b  = blockIdx.y;
    const int k0 = blockIdx.x * 32;
    const int tx = threadIdx.x;
    const int ty = threadIdx.y;
#pragma unroll
    for (int i = 0; i < 4; ++i) {
        const int r = ty + 8 * i;
        const float* src = X + ((size_t)b * NN + k0 + r) * FF;
        t[r][tx]      = src[tx];
        t[r][tx + 32] = src[tx + 32];
    }
    __syncthreads();
#pragma unroll
    for (int j = 0; j < 8; ++j) {
        const int f = ty + 8 * j;
        g_Xt[((size_t)b * FF + f) * NN + k0 + tx] = __float2half_rn(t[tx][f]);
    }
}

// ---------- main GEMM ----------
__global__ __launch_bounds__(256, 2) void gemm_f16_k128(
    const float* __restrict__ A,
    const float* __restrict__ bias,
    float* __restrict__ out)
{
    extern __shared__ char ds[];
    const uint32_t sb = smem_u32(ds);

    const int tid  = threadIdx.x;
    const int wid  = tid >> 5;
    const int lane = tid & 31;

    const int b  = blockIdx.x / CTAS_B;
    const int ct = blockIdx.x % CTAS_B;
    const int g0 = (ct * 256) / CTAS_B;
    const int g1 = ((ct + 1) * 256) / CTAS_B;
    const int NG = g1 - g0;             // 6 or 7 (16-row groups)
    const int nrows = NG * 16;

    const float*  Ab = A + ((size_t)b * NN + (size_t)g0 * 16) * NN;
    const __half* Xb = g_Xt + (size_t)b * FF * NN;

    // producer addressing (constant per thread)
    const int arow = tid >> 4;
    const int ac4  = tid & 15;
    const int brow = tid >> 3;
    const int bc   = tid & 7;
    const float*  a_ld = Ab + (size_t)arow * NN + ac4 * 4;
    const __half* b_ld = Xb + (size_t)brow * NN + bc * 8;
    const uint32_t a_sts = SW((uint32_t)(arow * 128 + ac4 * 8));   // + i*2048
    const uint32_t b_sts = SW((uint32_t)(brow * 128 + bc * 16));   // + i*4096

    // ldmatrix lane decomposition (within one 128B-row sub-tile, as R5)
    const int li = lane >> 3;
    const int lr = lane & 7;
    const uint32_t a_off =
        (uint32_t)((wid * 16 + (li & 1) * 8 + lr) * 128 + (li >> 1) * 16);
    const uint32_t b_off =
        (uint32_t)(((li >> 1) * 8 + lr) * 128 + (li & 1) * 16);

    float acc[8][4];
#pragma unroll
    for (int n = 0; n < 8; ++n)
#pragma unroll
        for (int j = 0; j < 4; ++j) acc[n][j] = 0.0f;

    float4 pa[MAXG];
    uint4  pb[2];

    // --- helpers (device lambdas) ---
    auto ldg_sub = [&](int s) {
        const size_t ko = (size_t)s * 64;
#pragma unroll
        for (int i = 0; i < MAXG; ++i)
            if (16 * i < nrows)
                pa[i] = *reinterpret_cast<const float4*>(
                    a_ld + (size_t)(16 * i) * NN + ko);
#pragma unroll
        for (int i = 0; i < 2; ++i)
            pb[i] = *reinterpret_cast<const uint4*>(
                b_ld + (size_t)(32 * i) * NN + ko);
    };
    auto sts_sub = [&](uint32_t abase, uint32_t bbase) {
#pragma unroll
        for (int i = 0; i < MAXG; ++i)
            if (16 * i < nrows) {
                __half2 h0 = __floats2half2_rn(pa[i].x, pa[i].y);
                __half2 h1 = __floats2half2_rn(pa[i].z, pa[i].w);
                asm volatile("st.shared.v2.b32 [%0], {%1, %2};"
                             :: "r"(abase + a_sts + (uint32_t)i * 2048),
                                "r"(*(uint32_t*)&h0), "r"(*(uint32_t*)&h1)
                             : "memory");
            }
#pragma unroll
        for (int i = 0; i < 2; ++i)
            asm volatile("st.shared.v4.b32 [%0], {%1,%2,%3,%4};"
                         :: "r"(bbase + b_sts + (uint32_t)i * 4096),
                            "r"(pb[i].x), "r"(pb[i].y), "r"(pb[i].z), "r"(pb[i].w)
                         : "memory");
    };
    auto compute_sub = [&](uint32_t abase, uint32_t bbase) {
#pragma unroll
        for (int ks = 0; ks < 4; ++ks) {
            uint32_t a0, a1, a2, a3;
            asm volatile(
                "ldmatrix.sync.aligned.m8n8.x4.shared.b16 {%0,%1,%2,%3}, [%4];"
                : "=r"(a0), "=r"(a1), "=r"(a2), "=r"(a3)
                : "r"(abase + SW(a_off + (uint32_t)ks * 32)));
#pragma unroll
            for (int p = 0; p < 4; ++p) {
                uint32_t b0, b1, b2, b3;
                asm volatile(
                    "ldmatrix.sync.aligned.m8n8.x4.shared.b16 {%0,%1,%2,%3}, [%4];"
                    : "=r"(b0), "=r"(b1), "=r"(b2), "=r"(b3)
                    : "r"(bbase + SW(b_off + (uint32_t)p * 2048 + (uint32_t)ks * 32)));
                asm volatile(
                    "mma.sync.aligned.m16n8k16.row.col.f32.f16.f16.f32 "
                    "{%0,%1,%2,%3}, {%4,%5,%6,%7}, {%8,%9}, {%0,%1,%2,%3};"
                    : "+f"(acc[2*p][0]), "+f"(acc[2*p][1]),
                      "+f"(acc[2*p][2]), "+f"(acc[2*p][3])
                    : "r"(a0), "r"(a1), "r"(a2), "r"(a3), "r"(b0), "r"(b1));
                asm volatile(
                    "mma.sync.aligned.m16n8k16.row.col.f32.f16.f16.f32 "
                    "{%0,%1,%2,%3}, {%4,%5,%6,%7}, {%8,%9}, {%0,%1,%2,%3};"
                    : "+f"(acc[2*p+1][0]), "+f"(acc[2*p+1][1]),
                      "+f"(acc[2*p+1][2]), "+f"(acc[2*p+1][3])
                    : "r"(a0), "r"(a1), "r"(a2), "r"(a3), "r"(b2), "r"(b3));
            }
        }
    };

    // ---- prologue: fill buffer 0 (subs 0,1), preload sub 2 ----
    ldg_sub(0);
    sts_sub(sb,          sb + OFF_B);
    ldg_sub(1);
    sts_sub(sb + SUB_A,  sb + OFF_B + SUB_B);
    ldg_sub(2);
    __syncthreads();

    for (int C = 0; C < NIT; ++C) {
        const uint32_t cur = sb + (uint32_t)(C & 1) * STB2;
        const uint32_t nxt = sb + (uint32_t)((C + 1) & 1) * STB2;

        // regs hold sub 2C+2 -> nxt.sub0 (consumers of nxt finished at last barrier)
        if (2 * C + 2 < NSUB) sts_sub(nxt, nxt + OFF_B);
        if (2 * C + 3 < NSUB) ldg_sub(2 * C + 3);

        if (wid < NG) compute_sub(cur, cur + OFF_B);               // sub 2C

        if (2 * C + 3 < NSUB) sts_sub(nxt + SUB_A, nxt + OFF_B + SUB_B);
        if (2 * C + 4 < NSUB) ldg_sub(2 * C + 4);

        if (wid < NG) compute_sub(cur + SUB_A, cur + OFF_B + SUB_B); // sub 2C+1

        __syncthreads();
    }

    // ---- epilogue: add bias, store ----
    if (wid < NG) {
        const int g = lane >> 2, q = lane & 3;
        const int mlo = (g0 + wid) * 16 + g;
        float* o0 = out + ((size_t)b * NN + mlo) * FF;
        float* o1 = o0 + (size_t)8 * FF;
#pragma unroll
        for (int nt = 0; nt < 8; ++nt) {
            const int col = nt * 8 + q * 2;
            const float2 bv = *reinterpret_cast<const float2*>(bias + col);
            float2 v0 = make_float2(acc[nt][0] + bv.x, acc[nt][1] + bv.y);
            float2 v1 = make_float2(acc[nt][2] + bv.x, acc[nt][3] + bv.y);
            *reinterpret_cast<float2*>(o0 + col) = v0;
            *reinterpret_cast<float2*>(o1 + col) = v1;
        }
    }
}

extern "C" void kernel_launch(void* const* d_in, const int* in_sizes, int n_in,
                              void* d_out, int out_size)
{
    const float* A    = (const float*)d_in[0]; // adjacent [8,4096,4096]
    const float* X    = (const float*)d_in[1]; // annotations [8,4096,64]
    const float* bias = (const float*)d_in[2]; // bias [1,1,64]
    float* out = (float*)d_out;

    cudaFuncSetAttribute(gemm_f16_k128,
                         cudaFuncAttributeMaxDynamicSharedMemorySize, SMEM_DYN);

    dim3 pg(NN / 32, NBATCH);
    dim3 pbk(32, 8);
    prep_xt_kernel<<<pg, pbk>>>(X);

    gemm_f16_k128<<<NBATCH * CTAS_B, 256, SMEM_DYN>>>(A, bias, out);
}